// round 9
// baseline (speedup 1.0000x reference)
#include <cuda_runtime.h>
#include <cuda_bf16.h>
#include <math_constants.h>
#include <cstdint>

// Problem constants
#define NB      32
#define DIM     64
#define HW      4096
#define N_ROWS  (NB * HW)       // 131072
#define N_CODES 1024
#define N_ELEMS (N_ROWS * DIM)  // 8388608

#define KSPLIT  192             // [zh | zl | zh] . [eh | eh | el]
#define TILE_N  128
#define N_CTILES (N_CODES / TILE_N)  // 8
#define MARGIN  3e-5f
#define AS      200             // bf16 elems per smem row (stride 400 B)

#define K2_BLOCKS  512
#define K2_THREADS 1024

// SMEM layout (dynamic)
#define SM_HS2_OFF 0
#define SM_A_OFF   4096
#define SM_B_OFF   55296
#define SM_M1_OFF  106496      // float [8][32]
#define SM_M2_OFF  107520      // float [8][32]
#define SM_I1_OFF  108544      // int   [8][32]
#define SMEM_TOTAL 109568

// Device scratch
__device__ int            g_best_idx[N_ROWS];
__device__ double         g_partials[K2_BLOCKS];
__device__ float          g_s2[N_CODES];
__device__ float          g_half_s2[N_CODES];
__device__ __nv_bfloat16  g_Bsplit[N_CODES * KSPLIT];
__device__ int            g_nflag;
__device__ int            g_flag_list[N_ROWS];

__device__ __forceinline__ uint32_t smem_u32(const void* p) {
    uint32_t a;
    asm("{ .reg .u64 t; cvta.to.shared.u64 t, %1; cvt.u32.u64 %0, t; }"
        : "=r"(a) : "l"(p));
    return a;
}

// ---------------------------------------------------------------------------
// Kernel 0 (prep): exact per-code s2 (R5 sequential chain), half_s2, and the
// bf16 split codebook g_Bsplit[c] = [eh(64) | eh(64) | el(64)].
// ---------------------------------------------------------------------------
__global__ void __launch_bounds__(256)
vq_prep_kernel(const float* __restrict__ cb)
{
    const int c = blockIdx.x * 256 + threadIdx.x;
    if (c == 0) g_nflag = 0;
    if (c >= N_CODES) return;
    const float* ep = cb + (size_t)c * DIM;
    float acc = 0.0f;
    #pragma unroll
    for (int k = 0; k < DIM; k++) {
        float e = ep[k];
        acc = __fadd_rn(acc, __fmul_rn(e, e));
        __nv_bfloat16 eh = __float2bfloat16(e);
        __nv_bfloat16 el = __float2bfloat16(__fadd_rn(e, -__bfloat162float(eh)));
        g_Bsplit[(size_t)c * KSPLIT + k]       = eh;
        g_Bsplit[(size_t)c * KSPLIT + 64 + k]  = eh;
        g_Bsplit[(size_t)c * KSPLIT + 128 + k] = el;
    }
    g_s2[c] = acc;
    g_half_s2[c] = __fmul_rn(0.5f, acc);
}

// ---------------------------------------------------------------------------
// Kernel 1: HMMA (mma.sync bf16) cross GEMM + top-2 margin argmin.
// Grid: 1024 CTAs x 256 threads (8 warps). CTA handles 128 rows x all codes.
// Warp tile: 32 rows x 64 codes; warps w and w^1 share rows and split codes,
// merged at the end via smem (R8's missing step — both used to write the row).
// ---------------------------------------------------------------------------
__global__ void __launch_bounds__(256, 1)
vq_mma_argmin(const float* __restrict__ z)
{
    extern __shared__ char smem[];
    float* s_hs2 = (float*)(smem + SM_HS2_OFF);
    __nv_bfloat16* pA = (__nv_bfloat16*)(smem + SM_A_OFF);
    float* s_m1 = (float*)(smem + SM_M1_OFF);
    float* s_m2 = (float*)(smem + SM_M2_OFF);
    int*   s_i1 = (int*)(smem + SM_I1_OFF);
    const uint32_t sbase = smem_u32(smem);
    const uint32_t sA = sbase + SM_A_OFF;
    const uint32_t sB = sbase + SM_B_OFF;

    const int tid  = threadIdx.x;
    const int lane = tid & 31;
    const int w    = tid >> 5;
    const int ct   = blockIdx.x;

    // stage half_s2
    #pragma unroll
    for (int i = 0; i < 4; i++) s_hs2[tid + i * 256] = g_half_s2[tid + i * 256];

    // stage A: row r = tid/2, k-half = (tid&1)*32. bf16 split -> [zh|zl|zh]
    {
        const int r  = tid >> 1;
        const int kh = (tid & 1) * 32;
        const int row = ct * 128 + r;
        const int b = row >> 12, hw = row & 4095;
        const float* zp = z + (size_t)b * (DIM * HW) + hw;
        __nv_bfloat16* arow = pA + r * AS;
        #pragma unroll
        for (int kk = 0; kk < 32; kk++) {
            int k = kh + kk;
            float v = zp[(size_t)k * HW];
            __nv_bfloat16 h = __float2bfloat16(v);
            __nv_bfloat16 l = __float2bfloat16(__fadd_rn(v, -__bfloat162float(h)));
            arow[k] = h; arow[64 + k] = l; arow[128 + k] = h;
        }
    }

    const int m0 = (w >> 1) * 32;   // warp M origin (0,32,64,96)
    const int n0 = (w & 1) * 64;    // warp N origin within 128-code tile

    // per-thread top-2 state for 4 row-slots (am*2 + rhalf)
    float m1[4], m2[4];
    int   i1[4];
    #pragma unroll
    for (int s = 0; s < 4; s++) { m1[s] = CUDART_INF_F; m2[s] = CUDART_INF_F; i1[s] = 0; }

    for (int tn = 0; tn < N_CTILES; tn++) {
        // stage B tile: code row cr = tid/2, half = tid&1 -> 96 bf16 = 12 uint4
        {
            const int cr = tid >> 1;
            const int half = tid & 1;
            const uint4* src = (const uint4*)((const char*)g_Bsplit
                + ((size_t)(tn * 128 + cr) * KSPLIT + half * 96) * 2);
            uint4* dst = (uint4*)(smem + SM_B_OFF + cr * (AS * 2) + half * 192);
            #pragma unroll
            for (int i = 0; i < 12; i++) dst[i] = src[i];
        }
        __syncthreads();

        float d[2][8][4];
        #pragma unroll
        for (int a = 0; a < 2; a++)
            #pragma unroll
            for (int b = 0; b < 8; b++)
                #pragma unroll
                for (int q = 0; q < 4; q++) d[a][b][q] = 0.0f;

        #pragma unroll
        for (int ks = 0; ks < KSPLIT / 16; ks++) {
            const int k = ks * 16;
            uint32_t af[2][4];
            #pragma unroll
            for (int am = 0; am < 2; am++) {
                uint32_t addr = sA
                    + (uint32_t)(m0 + am * 16 + (lane & 15)) * (AS * 2)
                    + (uint32_t)(((lane & 16) ? (k + 8) : k) * 2);
                asm volatile(
                    "ldmatrix.sync.aligned.m8n8.x4.shared.b16 {%0,%1,%2,%3}, [%4];"
                    : "=r"(af[am][0]), "=r"(af[am][1]), "=r"(af[am][2]), "=r"(af[am][3])
                    : "r"(addr));
            }
            uint32_t bf0[8], bf1[8];
            #pragma unroll
            for (int bn = 0; bn < 8; bn++) {
                uint32_t addr = sB
                    + (uint32_t)(n0 + bn * 8 + (lane & 7)) * (AS * 2)
                    + (uint32_t)(((lane & 8) ? (k + 8) : k) * 2);
                asm volatile(
                    "ldmatrix.sync.aligned.m8n8.x2.shared.b16 {%0,%1}, [%2];"
                    : "=r"(bf0[bn]), "=r"(bf1[bn])
                    : "r"(addr));
            }
            #pragma unroll
            for (int am = 0; am < 2; am++)
                #pragma unroll
                for (int bn = 0; bn < 8; bn++) {
                    asm volatile(
                        "mma.sync.aligned.m16n8k16.row.col.f32.bf16.bf16.f32 "
                        "{%0,%1,%2,%3}, {%4,%5,%6,%7}, {%8,%9}, {%0,%1,%2,%3};"
                        : "+f"(d[am][bn][0]), "+f"(d[am][bn][1]),
                          "+f"(d[am][bn][2]), "+f"(d[am][bn][3])
                        : "r"(af[am][0]), "r"(af[am][1]), "r"(af[am][2]), "r"(af[am][3]),
                          "r"(bf0[bn]), "r"(bf1[bn]));
                }
        }
        __syncthreads();   // ldmatrix reads done before next tile's B writes

        // epilogue: val = half_s2[code] - cross ; per-row-slot top-2
        const int code0 = tn * TILE_N;
        #pragma unroll
        for (int am = 0; am < 2; am++) {
            #pragma unroll
            for (int bn = 0; bn < 8; bn++) {
                const int cbase = code0 + n0 + bn * 8 + (lane & 3) * 2;
                #pragma unroll
                for (int q = 0; q < 4; q++) {
                    const int slot = am * 2 + (q >> 1);
                    const int code = cbase + (q & 1);
                    float v = __fadd_rn(s_hs2[code], -d[am][bn][q]);
                    if (v < m1[slot]) { m2[slot] = m1[slot]; m1[slot] = v; i1[slot] = code; }
                    else if (v < m2[slot]) { m2[slot] = v; }
                }
            }
        }
    }

    // intra-warp quad reduction (lanes in a quad hold different codes, same rows)
    #pragma unroll
    for (int off = 1; off <= 2; off <<= 1) {
        #pragma unroll
        for (int s = 0; s < 4; s++) {
            float om1 = __shfl_xor_sync(0xffffffffu, m1[s], off);
            float om2 = __shfl_xor_sync(0xffffffffu, m2[s], off);
            int   oi1 = __shfl_xor_sync(0xffffffffu, i1[s], off);
            if (om1 < m1[s]) {
                m2[s] = fminf(m1[s], om2);
                m1[s] = om1; i1[s] = oi1;
            } else {
                m2[s] = fminf(m2[s], om1);
            }
        }
    }

    // publish per-warp per-row top-2 (warp covers rows m0..m0+31, code half n0)
    if ((lane & 3) == 0) {
        #pragma unroll
        for (int s = 0; s < 4; s++) {
            const int rl = (s >> 1) * 16 + (lane >> 2) + (s & 1) * 8;  // 0..31
            s_m1[w * 32 + rl] = m1[s];
            s_m2[w * 32 + rl] = m2[s];
            s_i1[w * 32 + rl] = i1[s];
        }
    }
    __syncthreads();

    // merge warp pairs (2p covers codes n0=0 half, 2p+1 the other) and emit
    if (tid < 128) {
        const int p  = tid >> 5;       // row group 0..3
        const int rl = tid & 31;
        const int ia = (2 * p) * 32 + rl;
        const int ib = (2 * p + 1) * 32 + rl;
        float a1 = s_m1[ia], a2 = s_m2[ia]; int ai = s_i1[ia];
        float b1 = s_m1[ib], b2 = s_m2[ib]; int bi = s_i1[ib];
        float t1, t2; int ti;
        if (a1 <= b1) { t1 = a1; ti = ai; t2 = fminf(a2, b1); }
        else          { t1 = b1; ti = bi; t2 = fminf(b2, a1); }
        const int row = ct * 128 + tid;
        if (__fadd_rn(t2, -t1) < MARGIN) {
            int q = atomicAdd(&g_nflag, 1);
            g_flag_list[q] = row;
        } else {
            g_best_idx[row] = ti;
        }
    }
}

// ---------------------------------------------------------------------------
// Kernel 2 (fallback): bit-exact R5-chain full argmin for flagged rows,
// warp-per-row. Ties -> smallest index (reference first-index rule).
// ---------------------------------------------------------------------------
__global__ void __launch_bounds__(256)
vq_exact_fallback(const float* __restrict__ z, const float* __restrict__ cb)
{
    const int lane = threadIdx.x & 31;
    const int warp_g = (blockIdx.x * 256 + threadIdx.x) >> 5;
    const int nwarps = (gridDim.x * 256) >> 5;
    const int n = g_nflag;

    for (int i = warp_g; i < n; i += nwarps) {
        const int row = g_flag_list[i];
        const int b = row >> 12, hw = row & 4095;
        const float* zp = z + (size_t)b * (DIM * HW) + hw;
        float zr[DIM];
        double s1d = 0.0;
        #pragma unroll
        for (int k = 0; k < DIM; k++) {
            float v = __ldg(zp + (size_t)k * HW);
            zr[k] = v;
            s1d += (double)__fmul_rn(v, v);
        }
        const float s1 = (float)s1d;

        float best = CUDART_INF_F;
        int   bidx = 0x7fffffff;
        for (int c = lane; c < N_CODES; c += 32) {
            const float4* ep = (const float4*)(cb + (size_t)c * DIM);
            float a0 = 0.f, a1 = 0.f, a2 = 0.f, a3 = 0.f;
            #pragma unroll
            for (int k = 0; k < DIM / 4; k++) {
                float4 e = __ldg(&ep[k]);
                a0 = fmaf(zr[4 * k + 0], e.x, a0);
                a1 = fmaf(zr[4 * k + 1], e.y, a1);
                a2 = fmaf(zr[4 * k + 2], e.z, a2);
                a3 = fmaf(zr[4 * k + 3], e.w, a3);
            }
            float cross = __fadd_rn(__fadd_rn(a0, a1), __fadd_rn(a2, a3));
            float tt    = __fadd_rn(s1, g_s2[c]);
            float score = __fmaf_rn(-2.0f, cross, tt);   // == RN(tt - 2*cross)
            if (score < best) { best = score; bidx = c; }
        }
        #pragma unroll
        for (int off = 16; off > 0; off >>= 1) {
            float ob = __shfl_down_sync(0xffffffffu, best, off);
            int   oi = __shfl_down_sync(0xffffffffu, bidx, off);
            if (ob < best || (ob == best && oi < bidx)) { best = ob; bidx = oi; }
        }
        if (lane == 0) g_best_idx[row] = bidx;
    }
}

// ---------------------------------------------------------------------------
// Kernel 3: gather + straight-through output + fp64 partial sums (proven)
// ---------------------------------------------------------------------------
__global__ void __launch_bounds__(K2_THREADS)
vq_apply_kernel(const float* __restrict__ z, const float* __restrict__ cb,
                float* __restrict__ out)
{
    __shared__ double s_warp[K2_THREADS / 32];
    const int tid  = threadIdx.x;
    const int lane = tid & 31;
    const int wid  = tid >> 5;
    const long long base = ((long long)blockIdx.x * K2_THREADS + tid) * 16;
    const int b   = (int)(base >> 18);
    const int cch = (int)(base >> 12) & 63;
    const int h   = (int)(base >> 6) & 63;
    const int ww  = (int)base & 63;
    const int row0 = b * HW + h * 64 + ww;

    double acc = 0.0;
    #pragma unroll
    for (int g = 0; g < 4; g++) {
        float4 zv = *(const float4*)(z + base + 4 * g);
        int4   iv = *(const int4*)(g_best_idx + row0 + 4 * g);
        float q0 = cb[iv.x * DIM + cch];
        float q1 = cb[iv.y * DIM + cch];
        float q2 = cb[iv.z * DIM + cch];
        float q3 = cb[iv.w * DIM + cch];
        float d0 = __fadd_rn(q0, -zv.x);
        float d1 = __fadd_rn(q1, -zv.y);
        float d2 = __fadd_rn(q2, -zv.z);
        float d3 = __fadd_rn(q3, -zv.w);
        float4 ov;
        ov.x = __fadd_rn(zv.x, d0);
        ov.y = __fadd_rn(zv.y, d1);
        ov.z = __fadd_rn(zv.z, d2);
        ov.w = __fadd_rn(zv.w, d3);
        *(float4*)(out + base + 4 * g) = ov;
        float sg = __fadd_rn(__fadd_rn(__fmul_rn(d0, d0), __fmul_rn(d1, d1)),
                             __fadd_rn(__fmul_rn(d2, d2), __fmul_rn(d3, d3)));
        acc += (double)sg;
    }
    #pragma unroll
    for (int off = 16; off > 0; off >>= 1)
        acc += __shfl_down_sync(0xffffffffu, acc, off);
    if (lane == 0) s_warp[wid] = acc;
    __syncthreads();
    if (wid == 0) {
        double v = s_warp[lane];
        #pragma unroll
        for (int off = 16; off > 0; off >>= 1)
            v += __shfl_down_sync(0xffffffffu, v, off);
        if (lane == 0) g_partials[blockIdx.x] = v;
    }
}

__global__ void __launch_bounds__(K2_BLOCKS)
vq_loss_kernel(float* __restrict__ out, long long loss_pos)
{
    __shared__ double s_buf[K2_BLOCKS];
    const int tid = threadIdx.x;
    s_buf[tid] = g_partials[tid];
    __syncthreads();
    #pragma unroll
    for (int s = K2_BLOCKS / 2; s > 0; s >>= 1) {
        if (tid < s) s_buf[tid] += s_buf[tid + s];
        __syncthreads();
    }
    if (tid == 0) {
        float m = (float)(s_buf[0] * (1.0 / (double)N_ELEMS));
        out[loss_pos] = __fadd_rn(m, __fmul_rn(0.25f, m));
    }
}

// ---------------------------------------------------------------------------
extern "C" void kernel_launch(void* const* d_in, const int* in_sizes, int n_in,
                              void* d_out, int out_size)
{
    const float* z  = (const float*)d_in[0];
    const float* cb = (const float*)d_in[1];
    float* out = (float*)d_out;

    cudaFuncSetAttribute(vq_mma_argmin,
                         cudaFuncAttributeMaxDynamicSharedMemorySize, SMEM_TOTAL);

    vq_prep_kernel<<<4, 256>>>(cb);
    vq_mma_argmin<<<N_ROWS / 128, 256, SMEM_TOTAL>>>(z);
    vq_exact_fallback<<<512, 256>>>(z, cb);
    vq_apply_kernel<<<K2_BLOCKS, K2_THREADS>>>(z, cb, out);

    long long loss_pos = (long long)out_size - 1;
    if (loss_pos < N_ELEMS) loss_pos = N_ELEMS;
    vq_loss_kernel<<<1, K2_BLOCKS>>>(out, loss_pos);
}

// round 10
// speedup vs baseline: 1.2745x; 1.2745x over previous
#include <cuda_runtime.h>
#include <math_constants.h>

// Problem constants
#define NB      32
#define DIM     64
#define HW      4096            // 64*64
#define N_ROWS  (NB * HW)       // 131072
#define N_CODES 1024
#define N_ELEMS (N_ROWS * DIM)  // 8388608

#define TILE_C  128
#define N_TILES (N_CODES / TILE_C)

#define K1_THREADS 128          // 4 warps; 3 CTAs/SM target
#define K2_BLOCKS  512
#define K2_THREADS 1024

// Device scratch (no allocations allowed)
__device__ int    g_best_idx[N_ROWS];
__device__ double g_partials[K2_BLOCKS];

// ---- packed fp32x2 helpers (sm_100+) ---------------------------------------
__device__ __forceinline__ void fma2(unsigned long long& d,
                                     unsigned long long a,
                                     unsigned long long b) {
    asm("fma.rn.f32x2 %0, %1, %2, %0;" : "+l"(d) : "l"(a), "l"(b));
}
__device__ __forceinline__ unsigned long long add2(unsigned long long a,
                                                   unsigned long long b) {
    unsigned long long r;
    asm("add.rn.f32x2 %0, %1, %2;" : "=l"(r) : "l"(a), "l"(b));
    return r;
}
__device__ __forceinline__ unsigned long long pack2(float lo, float hi) {
    unsigned long long r;
    asm("mov.b64 %0, {%1, %2};" : "=l"(r) : "f"(lo), "f"(hi));
    return r;
}
__device__ __forceinline__ void unpack2(unsigned long long p, float& lo, float& hi) {
    asm("mov.b64 {%0, %1}, %2;" : "=f"(lo), "=f"(hi) : "l"(p));
}

// ---------------------------------------------------------------------------
// Kernel 1: per-row argmin over 1024 codes, TWO rows per thread, 128-thread
// blocks with min 3 blocks/SM (12 warps) so the FFMA2 pipe — not LDS, not
// latency — is the binding resource.  Math chain identical to R5/R6
// (rel_err 0.0):  score_c = fmaf(-2, cross, RN(s1 + s2_c)),
// cross grouped into 4 f32x2 accumulators by j parity, lo+hi fold, strict <
// ascending-c tie-break.
// ---------------------------------------------------------------------------
__global__ void __launch_bounds__(K1_THREADS, 3)
vq_argmin_kernel(const float* __restrict__ z, const float* __restrict__ cb)
{
    __shared__ float s_cb[TILE_C][DIM];   // 32 KB
    __shared__ float s_s2[TILE_C];

    const int tid  = threadIdx.x;
    const int rowA = blockIdx.x * K1_THREADS + tid;   // 0 .. 65535
    const int rowB = rowA + (N_ROWS / 2);             // 65536 .. 131071

    const int bA = rowA >> 12, hwA = rowA & 4095;
    const int bB = rowB >> 12, hwB = rowB & 4095;
    const float* zpA = z + (size_t)bA * (DIM * HW) + hwA;
    const float* zpB = z + (size_t)bB * (DIM * HW) + hwB;

    unsigned long long zA[DIM / 2], zB[DIM / 2];
    double s1dA = 0.0, s1dB = 0.0;
    #pragma unroll
    for (int k = 0; k < DIM / 2; k++) {
        float a0 = zpA[(size_t)(2 * k)     * HW];
        float a1 = zpA[(size_t)(2 * k + 1) * HW];
        s1dA += (double)__fmul_rn(a0, a0);
        s1dA += (double)__fmul_rn(a1, a1);
        zA[k] = pack2(a0, a1);
        float b0 = zpB[(size_t)(2 * k)     * HW];
        float b1 = zpB[(size_t)(2 * k + 1) * HW];
        s1dB += (double)__fmul_rn(b0, b0);
        s1dB += (double)__fmul_rn(b1, b1);
        zB[k] = pack2(b0, b1);
    }
    const float s1A = (float)s1dA;
    const float s1B = (float)s1dB;

    float bestA = CUDART_INF_F, bestB = CUDART_INF_F;
    int   idxA = 0, idxB = 0;

    for (int t = 0; t < N_TILES; t++) {
        __syncthreads();
        // Cooperative tile load: 128 codes * 64 floats = 2048 float4 / 128 thr
        const float4* src = (const float4*)(cb + (size_t)t * TILE_C * DIM);
        float4* dst = (float4*)&s_cb[0][0];
        #pragma unroll
        for (int i = 0; i < 16; i++) {
            dst[tid + i * K1_THREADS] = src[tid + i * K1_THREADS];
        }
        __syncthreads();
        // per-code |e|^2, exact sequential chain (tid covers all 128 codes)
        {
            float acc = 0.0f;
            #pragma unroll
            for (int k = 0; k < DIM; k++)
                acc = __fadd_rn(acc, __fmul_rn(s_cb[tid][k], s_cb[tid][k]));
            s_s2[tid] = acc;
        }
        __syncthreads();

        #pragma unroll 2
        for (int c = 0; c < TILE_C; c++) {
            const ulonglong2* ep = (const ulonglong2*)s_cb[c];
            unsigned long long A0 = 0ull, A1 = 0ull, A2 = 0ull, A3 = 0ull;
            unsigned long long B0 = 0ull, B1 = 0ull, B2 = 0ull, B3 = 0ull;
            #pragma unroll
            for (int j = 0; j < 16; j++) {
                ulonglong2 e = ep[j];
                if ((j & 1) == 0) {
                    fma2(A0, zA[2 * j],     e.x);
                    fma2(A1, zA[2 * j + 1], e.y);
                    fma2(B0, zB[2 * j],     e.x);
                    fma2(B1, zB[2 * j + 1], e.y);
                } else {
                    fma2(A2, zA[2 * j],     e.x);
                    fma2(A3, zA[2 * j + 1], e.y);
                    fma2(B2, zB[2 * j],     e.x);
                    fma2(B3, zB[2 * j + 1], e.y);
                }
            }
            const float s2c = s_s2[c];

            unsigned long long sa = add2(add2(A0, A1), add2(A2, A3));
            float loA, hiA; unpack2(sa, loA, hiA);
            float crossA = __fadd_rn(loA, hiA);
            float ttA    = __fadd_rn(s1A, s2c);
            float scoreA = __fmaf_rn(-2.0f, crossA, ttA);
            if (scoreA < bestA) { bestA = scoreA; idxA = t * TILE_C + c; }

            unsigned long long sb = add2(add2(B0, B1), add2(B2, B3));
            float loB, hiB; unpack2(sb, loB, hiB);
            float crossB = __fadd_rn(loB, hiB);
            float ttB    = __fadd_rn(s1B, s2c);
            float scoreB = __fmaf_rn(-2.0f, crossB, ttB);
            if (scoreB < bestB) { bestB = scoreB; idxB = t * TILE_C + c; }
        }
    }
    g_best_idx[rowA] = idxA;
    g_best_idx[rowB] = idxB;
}

// ---------------------------------------------------------------------------
// Kernel 2: gather + straight-through output + fp64 partial sums of (z_q - z)^2
// out = RN( z + RN(z_q - z) )  -- exact reference elementwise chain (proven)
// ---------------------------------------------------------------------------
__global__ void __launch_bounds__(K2_THREADS)
vq_apply_kernel(const float* __restrict__ z, const float* __restrict__ cb,
                float* __restrict__ out)
{
    __shared__ double s_warp[K2_THREADS / 32];

    const int tid  = threadIdx.x;
    const int lane = tid & 31;
    const int wid  = tid >> 5;
    const long long base = ((long long)blockIdx.x * K2_THREADS + tid) * 16;

    const int b   = (int)(base >> 18);
    const int cch = (int)(base >> 12) & 63;
    const int h   = (int)(base >> 6) & 63;
    const int w   = (int)base & 63;
    const int row0 = b * HW + h * 64 + w;

    double acc = 0.0;
    #pragma unroll
    for (int g = 0; g < 4; g++) {
        float4 zv = *(const float4*)(z + base + 4 * g);
        int4   iv = *(const int4*)(g_best_idx + row0 + 4 * g);

        float q0 = cb[iv.x * DIM + cch];
        float q1 = cb[iv.y * DIM + cch];
        float q2 = cb[iv.z * DIM + cch];
        float q3 = cb[iv.w * DIM + cch];

        float d0 = __fadd_rn(q0, -zv.x);
        float d1 = __fadd_rn(q1, -zv.y);
        float d2 = __fadd_rn(q2, -zv.z);
        float d3 = __fadd_rn(q3, -zv.w);

        float4 ov;
        ov.x = __fadd_rn(zv.x, d0);
        ov.y = __fadd_rn(zv.y, d1);
        ov.z = __fadd_rn(zv.z, d2);
        ov.w = __fadd_rn(zv.w, d3);
        *(float4*)(out + base + 4 * g) = ov;

        float sg = __fadd_rn(__fadd_rn(__fmul_rn(d0, d0), __fmul_rn(d1, d1)),
                             __fadd_rn(__fmul_rn(d2, d2), __fmul_rn(d3, d3)));
        acc += (double)sg;
    }

    #pragma unroll
    for (int off = 16; off > 0; off >>= 1)
        acc += __shfl_down_sync(0xffffffffu, acc, off);
    if (lane == 0) s_warp[wid] = acc;
    __syncthreads();
    if (wid == 0) {
        double v = s_warp[lane];
        #pragma unroll
        for (int off = 16; off > 0; off >>= 1)
            v += __shfl_down_sync(0xffffffffu, v, off);
        if (lane == 0) g_partials[blockIdx.x] = v;
    }
}

// ---------------------------------------------------------------------------
// Kernel 3: deterministic final reduction + loss
// ---------------------------------------------------------------------------
__global__ void __launch_bounds__(K2_BLOCKS)
vq_loss_kernel(float* __restrict__ out, long long loss_pos)
{
    __shared__ double s_buf[K2_BLOCKS];
    const int tid = threadIdx.x;
    s_buf[tid] = g_partials[tid];
    __syncthreads();
    #pragma unroll
    for (int s = K2_BLOCKS / 2; s > 0; s >>= 1) {
        if (tid < s) s_buf[tid] += s_buf[tid + s];
        __syncthreads();
    }
    if (tid == 0) {
        float m = (float)(s_buf[0] * (1.0 / (double)N_ELEMS));
        float v = __fadd_rn(m, __fmul_rn(0.25f, m));
        out[loss_pos] = v;
    }
}

// ---------------------------------------------------------------------------
extern "C" void kernel_launch(void* const* d_in, const int* in_sizes, int n_in,
                              void* d_out, int out_size)
{
    const float* z  = (const float*)d_in[0];   // [32, 64, 64, 64] fp32
    const float* cb = (const float*)d_in[1];   // [1024, 64] fp32
    float* out = (float*)d_out;                // [8388608 z_q_st] + [1 loss]

    vq_argmin_kernel<<<N_ROWS / (2 * K1_THREADS), K1_THREADS>>>(z, cb);
    vq_apply_kernel<<<K2_BLOCKS, K2_THREADS>>>(z, cb, out);

    long long loss_pos = (long long)out_size - 1;
    if (loss_pos < N_ELEMS) loss_pos = N_ELEMS;  // defensive; expect 8388609
    vq_loss_kernel<<<1, K2_BLOCKS>>>(out, loss_pos);
}

// round 11
// speedup vs baseline: 1.4181x; 1.1126x over previous
#include <cuda_runtime.h>
#include <math_constants.h>
#include <cstdint>

// Problem constants
#define NB      32
#define DIM     64
#define HW      4096            // 64*64
#define N_ROWS  (NB * HW)       // 131072
#define N_CODES 1024
#define N_ELEMS (N_ROWS * DIM)  // 8388608

#define N_TILES 16              // code tiles of 64
#define K2_BLOCKS  512
#define K2_THREADS 1024

// Dynamic smem layout for argmin kernel
#define SM_Z   0                // ulonglong [32][128] = 32768 B  (z pairs [k2][row])
#define SM_E   32768            // ulonglong [32][64]  = 16384 B  (code pairs [k2][c])
#define SM_S2  49152            // float [1024]        = 4096 B
#define SMEM_TOTAL 53248

// Device scratch (no allocations allowed)
__device__ int                g_best_idx[N_ROWS];
__device__ double             g_partials[K2_BLOCKS];
__device__ float              g_s2[N_CODES];
__device__ unsigned long long g_cbt[N_CODES * 32];   // [tile][k2][c] packed pairs

// ---- packed fp32x2 helpers (sm_100+) ---------------------------------------
__device__ __forceinline__ void fma2(unsigned long long& d,
                                     unsigned long long a,
                                     unsigned long long b) {
    asm("fma.rn.f32x2 %0, %1, %2, %0;" : "+l"(d) : "l"(a), "l"(b));
}
__device__ __forceinline__ unsigned long long pack2(float lo, float hi) {
    unsigned long long r;
    asm("mov.b64 %0, {%1, %2};" : "=l"(r) : "f"(lo), "f"(hi));
    return r;
}
__device__ __forceinline__ void unpack2(unsigned long long p, float& lo, float& hi) {
    asm("mov.b64 {%0, %1}, %2;" : "=f"(lo), "=f"(hi) : "l"(p));
}

// ---------------------------------------------------------------------------
// Kernel 0 (prep): exact per-code s2 (sequential fp32 chain, proven) and the
// pair-transposed codebook g_cbt[tile*2048 + k2*64 + cloc] = (e_{2k2}, e_{2k2+1}).
// ---------------------------------------------------------------------------
__global__ void __launch_bounds__(256)
vq_prep_kernel(const float* __restrict__ cb)
{
    const int c = blockIdx.x * 256 + threadIdx.x;
    if (c >= N_CODES) return;
    const float* ep = cb + (size_t)c * DIM;
    const int tbase = (c >> 6) * 2048 + (c & 63);
    float acc = 0.0f;
    #pragma unroll
    for (int k2 = 0; k2 < 32; k2++) {
        float e0 = ep[2 * k2];
        float e1 = ep[2 * k2 + 1];
        acc = __fadd_rn(acc, __fmul_rn(e0, e0));
        acc = __fadd_rn(acc, __fmul_rn(e1, e1));
        g_cbt[tbase + k2 * 64] = pack2(e0, e1);
    }
    g_s2[c] = acc;
}

// ---------------------------------------------------------------------------
// Kernel 1: register-tiled argmin. 1024 blocks x 256 threads; block covers 128
// rows x 1024 codes. Thread (ry=tid>>3, cx=tid&7) owns rows ry*4..+3 and codes
// {tn*64 + cx + 8j}. Both operands stream from smem as f32x2 (multicast LDS.64,
// conflict-free by construction). Score chain identical to the four passing
// rounds: score = fmaf(-2, cross, RN(s1 + s2)); cross = RN(lo + hi) of one
// f32x2 accumulator chain; strict < over ascending codes; cross-thread merge
// uses (score, min-index) so global first-index tie semantics are preserved.
// ---------------------------------------------------------------------------
__global__ void __launch_bounds__(256, 2)
vq_argmin_kernel(const float* __restrict__ z)
{
    extern __shared__ char smem[];
    unsigned long long* s_z  = (unsigned long long*)(smem + SM_Z);
    unsigned long long* s_e  = (unsigned long long*)(smem + SM_E);
    float*              s_s2 = (float*)(smem + SM_S2);
    float*              s_zf = (float*)(smem + SM_Z);

    const int tid = threadIdx.x;
    const int ry  = tid >> 3;     // 0..31  -> rows ry*4..ry*4+3
    const int cx  = tid & 7;      // 0..7   -> code lane
    const int r0  = blockIdx.x * 128;
    const int b   = r0 >> 12;
    const int hw0 = r0 & 4095;

    // stage s2 table
    #pragma unroll
    for (int i = 0; i < 4; i++) s_s2[tid + i * 256] = g_s2[tid + i * 256];

    // stage z tile as pairs [k2][row] (coalesced gmem reads)
    const float* zb = z + (size_t)b * (DIM * HW) + hw0;
    #pragma unroll
    for (int i = 0; i < 8; i++) {
        int idx = tid + i * 256;         // 0..2047
        int k = idx >> 5;                // dim
        int g = idx & 31;                // group of 4 rows
        float4 v = *(const float4*)(zb + (size_t)k * HW + g * 4);
        int base = ((k >> 1) * 128 + g * 4) * 2 + (k & 1);
        s_zf[base]     = v.x;
        s_zf[base + 2] = v.y;
        s_zf[base + 4] = v.z;
        s_zf[base + 6] = v.w;
    }
    __syncthreads();

    // exact s1 per owned row: fp64 sum of fp32 squares, ascending k (proven)
    float s1[4];
    #pragma unroll
    for (int i = 0; i < 4; i++) {
        const int row = ry * 4 + i;
        double acc = 0.0;
        #pragma unroll
        for (int k2 = 0; k2 < 32; k2++) {
            float lo, hi; unpack2(s_z[k2 * 128 + row], lo, hi);
            acc += (double)__fmul_rn(lo, lo);
            acc += (double)__fmul_rn(hi, hi);
        }
        s1[i] = (float)acc;
    }

    unsigned long long acc[4][8];
    #pragma unroll
    for (int i = 0; i < 4; i++)
        #pragma unroll
        for (int j = 0; j < 8; j++) acc[i][j] = 0ull;

    float best[4];
    int   bidx[4];
    #pragma unroll
    for (int i = 0; i < 4; i++) { best[i] = CUDART_INF_F; bidx[i] = 0; }

    for (int tn = 0; tn < N_TILES; tn++) {
        // stage code tile [k2][c] (contiguous, coalesced)
        const unsigned long long* src = g_cbt + tn * 2048;
        #pragma unroll
        for (int i = 0; i < 8; i++)
            s_e[tid + i * 256] = src[tid + i * 256];
        __syncthreads();

        #pragma unroll 8
        for (int k2 = 0; k2 < 32; k2++) {
            unsigned long long zr[4], er[8];
            #pragma unroll
            for (int i = 0; i < 4; i++) zr[i] = s_z[k2 * 128 + ry * 4 + i];
            #pragma unroll
            for (int j = 0; j < 8; j++) er[j] = s_e[k2 * 64 + cx + 8 * j];
            #pragma unroll
            for (int i = 0; i < 4; i++)
                #pragma unroll
                for (int j = 0; j < 8; j++)
                    fma2(acc[i][j], zr[i], er[j]);
        }

        // epilogue: fold + compare (codes ascending in j per thread)
        const int c0 = tn * 64 + cx;
        #pragma unroll
        for (int i = 0; i < 4; i++) {
            #pragma unroll
            for (int j = 0; j < 8; j++) {
                float lo, hi; unpack2(acc[i][j], lo, hi);
                float cross = __fadd_rn(lo, hi);
                const int code = c0 + 8 * j;
                float tt    = __fadd_rn(s1[i], s_s2[code]);
                float score = __fmaf_rn(-2.0f, cross, tt);
                if (score < best[i]) { best[i] = score; bidx[i] = code; }
                acc[i][j] = 0ull;
            }
        }
        __syncthreads();   // reads done before next tile overwrites s_e
    }

    // merge across the 8 code lanes (same rows): min score, tie -> min index
    #pragma unroll
    for (int off = 1; off <= 4; off <<= 1) {
        #pragma unroll
        for (int i = 0; i < 4; i++) {
            float os = __shfl_down_sync(0xffffffffu, best[i], off);
            int   oi = __shfl_down_sync(0xffffffffu, bidx[i], off);
            if (os < best[i] || (os == best[i] && oi < bidx[i])) {
                best[i] = os; bidx[i] = oi;
            }
        }
    }
    if (cx == 0) {
        #pragma unroll
        for (int i = 0; i < 4; i++)
            g_best_idx[r0 + ry * 4 + i] = bidx[i];
    }
}

// ---------------------------------------------------------------------------
// Kernel 2: gather + straight-through output + fp64 partial sums (proven)
// ---------------------------------------------------------------------------
__global__ void __launch_bounds__(K2_THREADS)
vq_apply_kernel(const float* __restrict__ z, const float* __restrict__ cb,
                float* __restrict__ out)
{
    __shared__ double s_warp[K2_THREADS / 32];

    const int tid  = threadIdx.x;
    const int lane = tid & 31;
    const int wid  = tid >> 5;
    const long long base = ((long long)blockIdx.x * K2_THREADS + tid) * 16;

    const int b   = (int)(base >> 18);
    const int cch = (int)(base >> 12) & 63;
    const int h   = (int)(base >> 6) & 63;
    const int w   = (int)base & 63;
    const int row0 = b * HW + h * 64 + w;

    double acc = 0.0;
    #pragma unroll
    for (int g = 0; g < 4; g++) {
        float4 zv = *(const float4*)(z + base + 4 * g);
        int4   iv = *(const int4*)(g_best_idx + row0 + 4 * g);

        float q0 = cb[iv.x * DIM + cch];
        float q1 = cb[iv.y * DIM + cch];
        float q2 = cb[iv.z * DIM + cch];
        float q3 = cb[iv.w * DIM + cch];

        float d0 = __fadd_rn(q0, -zv.x);
        float d1 = __fadd_rn(q1, -zv.y);
        float d2 = __fadd_rn(q2, -zv.z);
        float d3 = __fadd_rn(q3, -zv.w);

        float4 ov;
        ov.x = __fadd_rn(zv.x, d0);
        ov.y = __fadd_rn(zv.y, d1);
        ov.z = __fadd_rn(zv.z, d2);
        ov.w = __fadd_rn(zv.w, d3);
        *(float4*)(out + base + 4 * g) = ov;

        float sg = __fadd_rn(__fadd_rn(__fmul_rn(d0, d0), __fmul_rn(d1, d1)),
                             __fadd_rn(__fmul_rn(d2, d2), __fmul_rn(d3, d3)));
        acc += (double)sg;
    }

    #pragma unroll
    for (int off = 16; off > 0; off >>= 1)
        acc += __shfl_down_sync(0xffffffffu, acc, off);
    if (lane == 0) s_warp[wid] = acc;
    __syncthreads();
    if (wid == 0) {
        double v = s_warp[lane];
        #pragma unroll
        for (int off = 16; off > 0; off >>= 1)
            v += __shfl_down_sync(0xffffffffu, v, off);
        if (lane == 0) g_partials[blockIdx.x] = v;
    }
}

// ---------------------------------------------------------------------------
// Kernel 3: deterministic final reduction + loss
// ---------------------------------------------------------------------------
__global__ void __launch_bounds__(K2_BLOCKS)
vq_loss_kernel(float* __restrict__ out, long long loss_pos)
{
    __shared__ double s_buf[K2_BLOCKS];
    const int tid = threadIdx.x;
    s_buf[tid] = g_partials[tid];
    __syncthreads();
    #pragma unroll
    for (int s = K2_BLOCKS / 2; s > 0; s >>= 1) {
        if (tid < s) s_buf[tid] += s_buf[tid + s];
        __syncthreads();
    }
    if (tid == 0) {
        float m = (float)(s_buf[0] * (1.0 / (double)N_ELEMS));
        float v = __fadd_rn(m, __fmul_rn(0.25f, m));
        out[loss_pos] = v;
    }
}

// ---------------------------------------------------------------------------
extern "C" void kernel_launch(void* const* d_in, const int* in_sizes, int n_in,
                              void* d_out, int out_size)
{
    const float* z  = (const float*)d_in[0];   // [32, 64, 64, 64] fp32
    const float* cb = (const float*)d_in[1];   // [1024, 64] fp32
    float* out = (float*)d_out;                // [8388608 z_q_st] + [1 loss]

    cudaFuncSetAttribute(vq_argmin_kernel,
                         cudaFuncAttributeMaxDynamicSharedMemorySize, SMEM_TOTAL);

    vq_prep_kernel<<<4, 256>>>(cb);
    vq_argmin_kernel<<<N_ROWS / 128, 256, SMEM_TOTAL>>>(z);
    vq_apply_kernel<<<K2_BLOCKS, K2_THREADS>>>(z, cb, out);

    long long loss_pos = (long long)out_size - 1;
    if (loss_pos < N_ELEMS) loss_pos = N_ELEMS;  // defensive; expect 8388609
    vq_loss_kernel<<<1, K2_BLOCKS>>>(out, loss_pos);
}